// round 1
// baseline (speedup 1.0000x reference)
#include <cuda_runtime.h>
#include <cstdint>

// ---------------- problem constants (fixed by dataset) ----------------
// M = B*S = 4096, K = D = 768, N = V = 50257
#define MAX_M 4096
#define MAX_K 768
#define MAX_N 50257

#define BM 128
#define BN 128
#define BK 32
#define PAD 4
#define LDSTRIDE (BK + PAD)            // 36 floats
#define TILE_FLOATS (BM * LDSTRIDE)    // 4608 floats
#define SMEM_BYTES (4 * TILE_FLOATS * 4)  // A0 A1 B0 B1 = 73728 B

// Scratch (static device arrays: the sanctioned no-alloc path)
__device__ float g_h[MAX_M * MAX_K];      // tf32-rounded normalized activations [M,K]
__device__ float g_bt[MAX_N * MAX_K];     // tf32-rounded W_out [N,K]

__device__ __forceinline__ uint32_t f2tf32(float x) {
    uint32_t r;
    asm("cvt.rna.tf32.f32 %0, %1;" : "=r"(r) : "f"(x));
    return r;
}

__device__ __forceinline__ void cp_async16(uint32_t sdst, const void* gsrc, int srcBytes) {
    asm volatile("cp.async.cg.shared.global [%0], [%1], 16, %2;\n"
                 :: "r"(sdst), "l"(gsrc), "r"(srcBytes));
}

// ---------------- kernel 1: convert W_out -> tf32 bits ----------------
__global__ void cvt_b_kernel(const float4* __restrict__ src, int n4) {
    int i = blockIdx.x * blockDim.x + threadIdx.x;
    int stride = gridDim.x * blockDim.x;
    uint4* dst = reinterpret_cast<uint4*>(g_bt);
    for (; i < n4; i += stride) {
        float4 v = src[i];
        uint4 o;
        o.x = f2tf32(v.x); o.y = f2tf32(v.y);
        o.z = f2tf32(v.z); o.w = f2tf32(v.w);
        dst[i] = o;
    }
}

// ---------- kernel 2: fused gather + RMSNorm + tf32 convert ----------
__global__ void rmsnorm_kernel(const int* __restrict__ tok,
                               const float* __restrict__ emb,
                               const float* __restrict__ w, int D) {
    int row = blockIdx.x;
    int t = tok[row];
    const float* e = emb + (size_t)t * D;

    float ss = 0.f;
    for (int i = threadIdx.x; i < D; i += blockDim.x) {
        float v = e[i];
        ss += v * v;
    }
    __shared__ float red[8];
    #pragma unroll
    for (int o = 16; o > 0; o >>= 1) ss += __shfl_xor_sync(~0u, ss, o);
    if ((threadIdx.x & 31) == 0) red[threadIdx.x >> 5] = ss;
    __syncthreads();
    if (threadIdx.x < 8) {
        float v = red[threadIdx.x];
        #pragma unroll
        for (int o = 4; o > 0; o >>= 1) v += __shfl_xor_sync(0xffu, v, o);
        if (threadIdx.x == 0) red[0] = v;
    }
    __syncthreads();
    float scale = rsqrtf(red[0] / (float)D + 1e-5f);

    uint32_t* out = reinterpret_cast<uint32_t*>(g_h) + (size_t)row * D;
    for (int i = threadIdx.x; i < D; i += blockDim.x) {
        out[i] = f2tf32(e[i] * scale * w[i]);
    }
}

// ---------------- kernel 3: tf32 mma.sync GEMM ----------------
// C[M,N] = g_h[M,K] * g_bt[N,K]^T
__global__ void __launch_bounds__(256)
gemm_kernel(float* __restrict__ C, int M, int N, int K) {
    extern __shared__ float smem[];
    float* Asm[2] = { smem, smem + TILE_FLOATS };
    float* Bsm[2] = { smem + 2 * TILE_FLOATS, smem + 3 * TILE_FLOATS };

    const int tid  = threadIdx.x;
    const int lane = tid & 31;
    const int warp = tid >> 5;
    const int warp_m = warp & 3;      // 0..3 -> 32-row slab
    const int warp_n = warp >> 2;     // 0..1 -> 64-col slab
    const int g = lane >> 2;          // groupID
    const int t = lane & 3;           // threadID in group

    const int m0 = blockIdx.x * BM;
    const int n0 = blockIdx.y * BN;

    const int lr = tid >> 3;          // 0..31 row within pass
    const int lc = (tid & 7) * 4;     // float col offset (16B granules)

    const float* A  = g_h;
    const float* Bt = g_bt;

    float acc[2][8][4];
    #pragma unroll
    for (int mt = 0; mt < 2; mt++)
        #pragma unroll
        for (int nt = 0; nt < 8; nt++)
            #pragma unroll
            for (int i = 0; i < 4; i++) acc[mt][nt][i] = 0.f;

    const int KT = K / BK;   // 24

    auto load_tile = [&](int stage, int kt) {
        int k0 = kt * BK;
        #pragma unroll
        for (int p = 0; p < 4; p++) {
            int r = lr + p * 32;
            uint32_t sa = (uint32_t)__cvta_generic_to_shared(&Asm[stage][r * LDSTRIDE + lc]);
            cp_async16(sa, A + (size_t)(m0 + r) * K + k0 + lc, 16);
            int v = n0 + r;
            int ok = (v < N);
            uint32_t sb = (uint32_t)__cvta_generic_to_shared(&Bsm[stage][r * LDSTRIDE + lc]);
            cp_async16(sb, Bt + (size_t)(ok ? v : 0) * K + k0 + lc, ok ? 16 : 0);
        }
        asm volatile("cp.async.commit_group;\n");
    };

    auto compute = [&](int stage) {
        const float* as = Asm[stage];
        const float* bs = Bsm[stage];
        #pragma unroll
        for (int ks = 0; ks < 4; ks++) {
            int kb = ks * 8;
            uint32_t af[2][4];
            #pragma unroll
            for (int mt = 0; mt < 2; mt++) {
                int rm = warp_m * 32 + mt * 16 + g;
                af[mt][0] = __float_as_uint(as[(rm    ) * LDSTRIDE + kb + t    ]);
                af[mt][1] = __float_as_uint(as[(rm + 8) * LDSTRIDE + kb + t    ]);
                af[mt][2] = __float_as_uint(as[(rm    ) * LDSTRIDE + kb + t + 4]);
                af[mt][3] = __float_as_uint(as[(rm + 8) * LDSTRIDE + kb + t + 4]);
            }
            #pragma unroll
            for (int nt = 0; nt < 8; nt++) {
                int rn = warp_n * 64 + nt * 8 + g;
                uint32_t b0 = __float_as_uint(bs[rn * LDSTRIDE + kb + t    ]);
                uint32_t b1 = __float_as_uint(bs[rn * LDSTRIDE + kb + t + 4]);
                #pragma unroll
                for (int mt = 0; mt < 2; mt++) {
                    asm volatile(
                        "mma.sync.aligned.m16n8k8.row.col.f32.tf32.tf32.f32 "
                        "{%0,%1,%2,%3}, {%4,%5,%6,%7}, {%8,%9}, {%0,%1,%2,%3};\n"
                        : "+f"(acc[mt][nt][0]), "+f"(acc[mt][nt][1]),
                          "+f"(acc[mt][nt][2]), "+f"(acc[mt][nt][3])
                        : "r"(af[mt][0]), "r"(af[mt][1]),
                          "r"(af[mt][2]), "r"(af[mt][3]),
                          "r"(b0), "r"(b1));
                }
            }
        }
    };

    load_tile(0, 0);
    for (int kt = 0; kt < KT; kt++) {
        int cur = kt & 1;
        if (kt + 1 < KT) {
            load_tile(cur ^ 1, kt + 1);
            asm volatile("cp.async.wait_group 1;\n");
        } else {
            asm volatile("cp.async.wait_group 0;\n");
        }
        __syncthreads();
        compute(cur);
        __syncthreads();
    }

    // Epilogue: guarded scalar stores (N is odd -> float2 can misalign)
    #pragma unroll
    for (int mt = 0; mt < 2; mt++) {
        int row0 = m0 + warp_m * 32 + mt * 16 + g;
        #pragma unroll
        for (int nt = 0; nt < 8; nt++) {
            int col = n0 + warp_n * 64 + nt * 8 + t * 2;
            if (col < N) {
                C[(size_t)row0 * N + col]       = acc[mt][nt][0];
                C[(size_t)(row0 + 8) * N + col] = acc[mt][nt][2];
                if (col + 1 < N) {
                    C[(size_t)row0 * N + col + 1]       = acc[mt][nt][1];
                    C[(size_t)(row0 + 8) * N + col + 1] = acc[mt][nt][3];
                }
            }
        }
    }
}

// ---------------------------------------------------------------------
extern "C" void kernel_launch(void* const* d_in, const int* in_sizes, int n_in,
                              void* d_out, int out_size) {
    const int*   tok  = (const int*)d_in[0];    // [M] int32 token ids
    const float* emb  = (const float*)d_in[1];  // [V,D]
    const float* w    = (const float*)d_in[2];  // [D]
    const float* wout = (const float*)d_in[3];  // [V,D]
    float* out = (float*)d_out;

    int M = in_sizes[0];
    int D = in_sizes[2];
    int N = in_sizes[3] / D;

    // 1) convert W_out to tf32 (V*D divisible by 4)
    int n4 = (N * D) / 4;
    cvt_b_kernel<<<2048, 256>>>((const float4*)wout, n4);

    // 2) fused gather + RMSNorm + tf32
    rmsnorm_kernel<<<M, 256>>>(tok, emb, w, D);

    // 3) GEMM (m-tiles fast-varying so W tiles are L2-shared across all m)
    cudaFuncSetAttribute(gemm_kernel, cudaFuncAttributeMaxDynamicSharedMemorySize, SMEM_BYTES);
    dim3 grid(M / BM, (N + BN - 1) / BN);
    gemm_kernel<<<grid, 256, SMEM_BYTES>>>(out, M, N, D);
}

// round 3
// speedup vs baseline: 2.7374x; 2.7374x over previous
#include <cuda_runtime.h>
#include <cuda_fp16.h>
#include <cstdint>

// ---------------- problem constants (fixed by dataset) ----------------
#define M_TOTAL 4096      // B*S
#define K_DIM   768       // D
#define N_TOTAL 50257     // V

#define BM 128
#define BN 128
#define BK 64             // fp16: 64 elems = 128B row (SW128-style swizzle)
#define KC (K_DIM / BK)   // 12
#define STAGES 3
#define THREADS 256

#define STAGE_BYTES (BM * 128 + BN * 128)   // A 16KB + B 16KB = 32768
#define SMEM_REQ (STAGES * STAGE_BYTES)     // 98304

// Scratch: fp16 activations and fp16 W_out (static device arrays = sanctioned path)
__device__ __align__(1024) __half g_h[M_TOTAL * K_DIM];
__device__ __align__(1024) __half g_bh[(size_t)N_TOTAL * K_DIM];

// ---------------- PTX helpers (baseline sm_80-class PTX only) ----------------
__device__ __forceinline__ uint32_t smem_u32(const void* p) {
    uint32_t a;
    asm("{ .reg .u64 t; cvta.to.shared.u64 t, %1; cvt.u32.u64 %0, t; }" : "=r"(a) : "l"(p));
    return a;
}
__device__ __forceinline__ void cp16(uint32_t sdst, const void* gsrc) {
    asm volatile("cp.async.cg.shared.global [%0], [%1], 16;" :: "r"(sdst), "l"(gsrc));
}
__device__ __forceinline__ void ldsm_x4(uint32_t& r0, uint32_t& r1, uint32_t& r2, uint32_t& r3,
                                        uint32_t addr) {
    asm volatile("ldmatrix.sync.aligned.m8n8.x4.shared.b16 {%0,%1,%2,%3}, [%4];"
                 : "=r"(r0), "=r"(r1), "=r"(r2), "=r"(r3) : "r"(addr));
}
__device__ __forceinline__ void mma16816(float* c, const uint32_t* a, uint32_t b0, uint32_t b1) {
    asm volatile(
        "mma.sync.aligned.m16n8k16.row.col.f32.f16.f16.f32 "
        "{%0,%1,%2,%3}, {%4,%5,%6,%7}, {%8,%9}, {%0,%1,%2,%3};"
        : "+f"(c[0]), "+f"(c[1]), "+f"(c[2]), "+f"(c[3])
        : "r"(a[0]), "r"(a[1]), "r"(a[2]), "r"(a[3]), "r"(b0), "r"(b1));
}

// ---------------- kernel 1: W_out fp32 -> fp16 ----------------
__global__ void cvt_b_kernel(const float4* __restrict__ src, int n4) {
    int i = blockIdx.x * blockDim.x + threadIdx.x;
    int stride = gridDim.x * blockDim.x;
    uint2* dst = reinterpret_cast<uint2*>(g_bh);
    for (; i < n4; i += stride) {
        float4 v = src[i];
        __half2 h0 = __floats2half2_rn(v.x, v.y);
        __half2 h1 = __floats2half2_rn(v.z, v.w);
        uint2 o;
        o.x = *reinterpret_cast<uint32_t*>(&h0);
        o.y = *reinterpret_cast<uint32_t*>(&h1);
        dst[i] = o;
    }
}

// ---------- kernel 2: fused gather + RMSNorm -> fp16 ----------
__global__ void rmsnorm_kernel(const int* __restrict__ tok,
                               const float* __restrict__ emb,
                               const float* __restrict__ w, int D) {
    int row = blockIdx.x;
    int t = tok[row];
    const float* e = emb + (size_t)t * D;

    float ss = 0.f;
    for (int i = threadIdx.x; i < D; i += blockDim.x) {
        float v = e[i];
        ss += v * v;
    }
    __shared__ float red[8];
    #pragma unroll
    for (int o = 16; o > 0; o >>= 1) ss += __shfl_xor_sync(~0u, ss, o);
    if ((threadIdx.x & 31) == 0) red[threadIdx.x >> 5] = ss;
    __syncthreads();
    if (threadIdx.x < 8) {
        float v = red[threadIdx.x];
        #pragma unroll
        for (int o = 4; o > 0; o >>= 1) v += __shfl_xor_sync(0xffu, v, o);
        if (threadIdx.x == 0) red[0] = v;
    }
    __syncthreads();
    float scale = rsqrtf(red[0] / (float)D + 1e-5f);

    __half* out = g_h + (size_t)row * D;
    for (int i = threadIdx.x; i < D; i += blockDim.x) {
        out[i] = __float2half_rn(e[i] * scale * w[i]);
    }
}

// ---------------- kernel 3: fp16 mma.sync GEMM ----------------
// C[M,N] = g_h[M,K] * g_bh[N,K]^T
// BM=128, BN=128, BK=64, 3-stage cp.async, 8 warps: warp tile 32x64
__global__ void __launch_bounds__(THREADS, 2)
gemm_kernel(float* __restrict__ C) {
    extern __shared__ char smem[];
    const uint32_t sb = smem_u32(smem);

    const int tid  = threadIdx.x;
    const int lane = tid & 31;
    const int w    = tid >> 5;
    const int warp_m = w & 3;      // 4 warps over M: 32 rows each
    const int warp_n = w >> 2;     // 2 warps over N: 64 cols each
    const int g = lane >> 2;       // groupID
    const int t = lane & 3;        // threadID in group

    const int m0 = blockIdx.x * BM;     // m fast-varying -> B tiles L2-shared
    const int n0 = blockIdx.y * BN;

    const char* Ab = reinterpret_cast<const char*>(g_h);
    const char* Bb = reinterpret_cast<const char*>(g_bh);

    // ---- global->smem loaders ----
    const int rbase = tid >> 3;            // 0..31
    const int colb  = (tid & 7) * 16;      // byte col in 128B row

    auto load = [&](int kc, int s) {
        uint32_t abase = sb + (uint32_t)s * STAGE_BYTES;
        uint32_t bbase = abase + BM * 128;
        #pragma unroll
        for (int p = 0; p < 4; p++) {
            int r = rbase + p * 32;
            uint32_t off = (uint32_t)(r * 128 + colb);
            cp16(abase + (off ^ ((off >> 3) & 0x70)),
                 Ab + (size_t)(m0 + r) * (K_DIM * 2) + kc * 128 + colb);
        }
        #pragma unroll
        for (int p = 0; p < 4; p++) {
            int r = rbase + p * 32;
            int rn = n0 + r; if (rn >= N_TOTAL) rn = N_TOTAL - 1;
            uint32_t off = (uint32_t)(r * 128 + colb);
            cp16(bbase + (off ^ ((off >> 3) & 0x70)),
                 Bb + (size_t)rn * (K_DIM * 2) + kc * 128 + colb);
        }
        asm volatile("cp.async.commit_group;");
    };

    // ---- ldmatrix address precompute (row offset + swizzle xor mask) ----
    // lanes 0-7: rows 0-7 k-chunk lo16B; 8-15: rows 8-15 lo; 16-23: rows 0-7 hi; 24-31: rows 8-15 hi
    const int lrow  = lane & 15;
    const int lkoff = (lane >> 4) << 4;    // 0 or 16 bytes
    uint32_t rowA[2], mskA[2];
    #pragma unroll
    for (int mt = 0; mt < 2; mt++) {
        uint32_t off = (uint32_t)((warp_m * 32 + mt * 16 + lrow) * 128 + lkoff);
        rowA[mt] = off;
        mskA[mt] = (off >> 3) & 0x70;
    }
    uint32_t rowB[4], mskB[4];
    #pragma unroll
    for (int np = 0; np < 4; np++) {
        uint32_t off = (uint32_t)((warp_n * 64 + np * 16 + lrow) * 128 + lkoff);
        rowB[np] = off;
        mskB[np] = (off >> 3) & 0x70;
    }

    float acc[2][8][4];
    #pragma unroll
    for (int mt = 0; mt < 2; mt++)
        #pragma unroll
        for (int nt = 0; nt < 8; nt++)
            #pragma unroll
            for (int i = 0; i < 4; i++) acc[mt][nt][i] = 0.f;

    auto compute = [&](int s) {
        const uint32_t abase = sb + (uint32_t)s * STAGE_BYTES;
        const uint32_t bbase = abase + BM * 128;
        #pragma unroll
        for (int ks = 0; ks < 4; ks++) {
            const uint32_t kadd = (uint32_t)(ks * 32);
            uint32_t a[2][4];
            #pragma unroll
            for (int mt = 0; mt < 2; mt++)
                ldsm_x4(a[mt][0], a[mt][1], a[mt][2], a[mt][3],
                        abase + ((rowA[mt] + kadd) ^ mskA[mt]));
            #pragma unroll
            for (int np = 0; np < 4; np++) {
                uint32_t b0, b1, b2, b3;   // b0/b2: ntile even (k lo/hi); b1/b3: ntile odd
                ldsm_x4(b0, b1, b2, b3, bbase + ((rowB[np] + kadd) ^ mskB[np]));
                #pragma unroll
                for (int mt = 0; mt < 2; mt++) {
                    mma16816(acc[mt][2 * np],     a[mt], b0, b2);
                    mma16816(acc[mt][2 * np + 1], a[mt], b1, b3);
                }
            }
        }
    };

    // ---- 3-stage pipeline ----
    load(0, 0);
    load(1, 1);
    for (int kc = 0; kc < KC; kc++) {
        if (kc < KC - 1) asm volatile("cp.async.wait_group 1;");
        else             asm volatile("cp.async.wait_group 0;");
        __syncthreads();
        if (kc + 2 < KC) load(kc + 2, (kc + 2) % STAGES);
        compute(kc % STAGES);
    }
    __syncthreads();   // protect smem reuse by epilogue

    // ---- epilogue: frags -> padded smem -> coalesced STG ----
    // per-warp buffer: 32 rows x 68 floats (272B row, pad kills bank conflicts)
    const uint32_t buf = sb + (uint32_t)w * (32 * 272);
    #pragma unroll
    for (int mt = 0; mt < 2; mt++) {
        #pragma unroll
        for (int nt = 0; nt < 8; nt++) {
            uint32_t ad = buf + (uint32_t)((mt * 16 + g) * 272 + (nt * 8 + 2 * t) * 4);
            asm volatile("st.shared.v2.f32 [%0], {%1,%2};"
                         :: "r"(ad), "f"(acc[mt][nt][0]), "f"(acc[mt][nt][1]) : "memory");
            asm volatile("st.shared.v2.f32 [%0], {%1,%2};"
                         :: "r"(ad + 8 * 272), "f"(acc[mt][nt][2]), "f"(acc[mt][nt][3]) : "memory");
        }
    }
    __syncwarp();

    const int gcol0 = n0 + warp_n * 64;
    #pragma unroll 4
    for (int r = 0; r < 32; r++) {
        size_t rb = (size_t)(m0 + warp_m * 32 + r) * N_TOTAL;
        #pragma unroll
        for (int p = 0; p < 2; p++) {
            int cl = p * 32 + lane;
            int col = gcol0 + cl;
            float v;
            asm volatile("ld.shared.f32 %0, [%1];"
                         : "=f"(v) : "r"(buf + (uint32_t)(r * 272 + cl * 4)));
            if (col < N_TOTAL) C[rb + col] = v;
        }
    }
}

// ---------------------------------------------------------------------
extern "C" void kernel_launch(void* const* d_in, const int* in_sizes, int n_in,
                              void* d_out, int out_size) {
    const int*   tok  = (const int*)d_in[0];    // [M] int32 token ids
    const float* emb  = (const float*)d_in[1];  // [V,D]
    const float* wn   = (const float*)d_in[2];  // [D]
    const float* wout = (const float*)d_in[3];  // [V,D]
    float* out = (float*)d_out;

    int M = in_sizes[0];
    int D = in_sizes[2];
    int N = in_sizes[3] / D;

    // 1) convert W_out to fp16
    int n4 = (N * D) / 4;
    cvt_b_kernel<<<2048, 256>>>((const float4*)wout, n4);

    // 2) fused gather + RMSNorm -> fp16
    rmsnorm_kernel<<<M, 256>>>(tok, emb, wn, D);

    // 3) fp16 mma.sync GEMM (m fast-varying: B tiles L2-shared)
    cudaFuncSetAttribute(gemm_kernel, cudaFuncAttributeMaxDynamicSharedMemorySize, SMEM_REQ);
    dim3 grid(M / BM, (N + BN - 1) / BN);
    gemm_kernel<<<grid, THREADS, SMEM_REQ>>>(out);
}